// round 11
// baseline (speedup 1.0000x reference)
#include <cuda_runtime.h>
#include <cstdint>
#include <cstddef>

typedef unsigned long long ull;

#define TS 2048
#define Y1_ELEMS ((size_t)TS * 64 * 256)

// scratch (allocation-free rule)
__device__ float g_gx[(size_t)TS * 64 * 1024];
__device__ float g_y0[(size_t)TS * 64 * 256];
// h exchange through L2: [buf][group][substream][k][bb]
__device__ float g_hx[2][16][2][256][2];
// per-layer, per-group, per-substream, PER-RANK flags (own 128B lines)
__device__ __align__(128) unsigned g_flag[2][16][2][8][32];
__device__ __align__(128) unsigned g_fin[2][16][32];

__device__ __forceinline__ ull fma2(ull a, ull b, ull c) {
    ull d; asm("fma.rn.f32x2 %0,%1,%2,%3;" : "=l"(d) : "l"(a), "l"(b), "l"(c)); return d;
}
__device__ __forceinline__ ull mul2(ull a, ull b) {
    ull d; asm("mul.rn.f32x2 %0,%1,%2;" : "=l"(d) : "l"(a), "l"(b)); return d;
}
__device__ __forceinline__ ull add2(ull a, ull b) {
    ull d; asm("add.rn.f32x2 %0,%1,%2;" : "=l"(d) : "l"(a), "l"(b)); return d;
}
__device__ __forceinline__ ull pk(float lo, float hi) {
    ull r; asm("mov.b64 %0,{%1,%2};" : "=l"(r) : "f"(lo), "f"(hi)); return r;
}
__device__ __forceinline__ void upk(ull a, float& x, float& y) {
    asm("mov.b64 {%0,%1},%2;" : "=f"(x), "=f"(y) : "l"(a));
}
__device__ __forceinline__ ull dup2(float x) {
    ull r; asm("mov.b64 %0,{%1,%1};" : "=l"(r) : "f"(x)); return r;
}
__device__ __forceinline__ float ex2f(float x) {
    float r; asm("ex2.approx.f32 %0,%1;" : "=f"(r) : "f"(x)); return r;
}
__device__ __forceinline__ float rcpf(float x) {
    float r; asm("rcp.approx.f32 %0,%1;" : "=f"(r) : "f"(x)); return r;
}
__device__ __forceinline__ float sigf(float x) {
    return rcpf(1.f + ex2f(-1.44269504f * x));
}
__device__ __forceinline__ float tanhap(float x) {
    float r; asm("tanh.approx.f32 %0,%1;" : "=f"(r) : "f"(x)); return r;
}
__device__ __forceinline__ unsigned ldacq(const unsigned* p) {
    unsigned v;
    asm volatile("ld.acquire.gpu.global.u32 %0,[%1];" : "=r"(v) : "l"(p) : "memory");
    return v;
}

// ---------------------------------------------------------------------------
// GEMM: g_gx[m][n] = A_row(m) . W[:,n] + bias[n],  M = TS*64, N = 1024
// mode 0: A_row(m) = x + ((m&63)*TS + (m>>6))*128, K=128
// mode 1: A_row(m) = g_y0 + m*256,                 K=256
// ---------------------------------------------------------------------------
__global__ void __launch_bounds__(256, 1)
gemm_k(const float* __restrict__ A, const float* __restrict__ W,
       const float* __restrict__ bias, int K, int mode)
{
    __shared__ float As[16][132];
    __shared__ float Bs[16][128];

    const int tid = threadIdx.x;
    const int n0 = blockIdx.x * 128;
    const int m0 = blockIdx.y * 128;

    const int ar = tid >> 1;
    const int ac = (tid & 1) * 8;
    const int m = m0 + ar;
    const float* arow = mode ? (g_y0 + (size_t)m * 256)
                             : (A + ((size_t)(m & 63) * TS + (m >> 6)) * 128);
    const float* wp = W + (size_t)(tid >> 4) * 1024 + n0 + (tid & 15) * 8;

    const int tm = tid >> 4, tn = tid & 15;

    ull acc[8][4];
#pragma unroll
    for (int i = 0; i < 8; ++i)
#pragma unroll
        for (int j = 0; j < 4; ++j) acc[i][j] = 0ull;

#pragma unroll 1
    for (int k0 = 0; k0 < K; k0 += 16) {
        float4 a0 = *(const float4*)(arow + k0 + ac);
        float4 a1 = *(const float4*)(arow + k0 + ac + 4);
        float4 w0 = *(const float4*)(wp + (size_t)k0 * 1024);
        float4 w1 = *(const float4*)(wp + (size_t)k0 * 1024 + 4);
        __syncthreads();
        As[ac + 0][ar] = a0.x; As[ac + 1][ar] = a0.y;
        As[ac + 2][ar] = a0.z; As[ac + 3][ar] = a0.w;
        As[ac + 4][ar] = a1.x; As[ac + 5][ar] = a1.y;
        As[ac + 6][ar] = a1.z; As[ac + 7][ar] = a1.w;
        *(float4*)&Bs[tid >> 4][(tid & 15) * 8] = w0;
        *(float4*)&Bs[tid >> 4][(tid & 15) * 8 + 4] = w1;
        __syncthreads();
#pragma unroll
        for (int kk = 0; kk < 16; ++kk) {
            float4 av0 = *(const float4*)&As[kk][tm * 8];
            float4 av1 = *(const float4*)&As[kk][tm * 8 + 4];
            float av[8] = {av0.x, av0.y, av0.z, av0.w, av1.x, av1.y, av1.z, av1.w};
            const ull* bp = (const ull*)&Bs[kk][0];
            ull bv[4];
#pragma unroll
            for (int c = 0; c < 4; ++c) bv[c] = bp[tn * 4 + c];
#pragma unroll
            for (int r = 0; r < 8; ++r) {
                ull a2 = dup2(av[r]);
#pragma unroll
                for (int c = 0; c < 4; ++c) acc[r][c] = fma2(a2, bv[c], acc[r][c]);
            }
        }
    }

    float bb[8];
#pragma unroll
    for (int c = 0; c < 8; ++c) bb[c] = bias[n0 + tn * 8 + c];

#pragma unroll
    for (int r = 0; r < 8; ++r) {
        float v[8];
#pragma unroll
        for (int c = 0; c < 4; ++c) upk(acc[r][c], v[2 * c], v[2 * c + 1]);
#pragma unroll
        for (int c = 0; c < 8; ++c) v[c] += bb[c];
        float* op = g_gx + (size_t)(m0 + tm * 8 + r) * 1024 + n0 + tn * 8;
        *(float4*)op = make_float4(v[0], v[1], v[2], v[3]);
        *(float4*)(op + 4) = make_float4(v[4], v[5], v[6], v[7]);
    }
}

// ---------------------------------------------------------------------------
// Recurrence with 2-substream pipeline.
// 128 CTAs; group g = blockIdx>>3 (8 CTAs), rank r = blockIdx&7.
// Group handles batches [g*4, g*4+4): substream ss=0 -> (b0,b1), ss=1 -> (b2,b3).
// Rank owns hidden units [r*32, r*32+32); warp w owns 4 units.
// Lane k-chunk: k = i*32 + lane. Accumulators per substep: v[16] =
// 8 col-pairs x 2 batches; reduce-scatter butterfly (4 rounds + merge) leaves
// lane l with combo a = l&15: u=a>>2, gp=(a>>1)&1, bb=a&1.
// While substream B computes, substream A's L2 flag/h propagate -> the
// cross-CTA round trip is hidden behind one substep of compute.
// Consumer wait is PER-WARP (lanes 0..7 poll one rank flag each + syncwarp);
// producer side: bar.sync (all h stores done) then tid0 st.release flag.
// ---------------------------------------------------------------------------
__global__ void __launch_bounds__(256, 1)
recur_k(const float* __restrict__ whh, float* __restrict__ out, int layer)
{
    const int tid  = threadIdx.x;
    const int w    = tid >> 5;
    const int lane = tid & 31;
    const int grp  = blockIdx.x >> 3;
    const int r    = blockIdx.x & 7;
    const int gb0  = grp * 4;

    // epilogue identity from butterfly output combo a = lane & 15
    const int a_   = lane & 15;
    const int u    = a_ >> 2;
    const int gp   = (a_ >> 1) & 1;          // 0 -> (f,i), 1 -> (o,g)
    const int bb   = a_ & 1;
    const int jj   = r * 32 + w * 4 + u;
    const int colA = (2 * gp) * 256 + jj;
    const bool estore = (lane < 16) && (gp == 0);

    // weights: wreg[i][cp] for k = i*32 + lane, col pair (cA, cA+256)
    ull wreg[8][8];
#pragma unroll
    for (int i = 0; i < 8; ++i) {
        const int k = i * 32 + lane;
#pragma unroll
        for (int cpi = 0; cpi < 8; ++cpi) {
            const int cA = (2 * (cpi & 1)) * 256 + r * 32 + w * 4 + (cpi >> 1);
            const float* wp = whh + (size_t)k * 1024 + cA;
            wreg[i][cpi] = pk(wp[0], wp[256]);
        }
    }

    unsigned* fin = &g_fin[layer][grp][0];

    float cst[2] = {0.f, 0.f};
    float* yout = layer ? out : g_y0;
    float* hn = out + Y1_ELEMS + (size_t)layer * 16384;
    float* cn = out + Y1_ELEMS + 32768 + (size_t)layer * 16384;

    // gates_x pipeline (one packed pair per substream)
    ull gxr[2], gxn[2] = {0ull, 0ull};
#pragma unroll
    for (int ss = 0; ss < 2; ++ss) {
        const float* gpx = g_gx + ((size_t)(TS - 1) * 64 + gb0 + ss * 2 + bb) * 1024 + colA;
        gxr[ss] = pk(__ldg(gpx), __ldg(gpx + 256));
    }

#pragma unroll 1
    for (int s = 0; s < TS; ++s) {
        const int cur = s & 1;
        const int nxt = cur ^ 1;

        if (s + 1 < TS) {
#pragma unroll
            for (int ss = 0; ss < 2; ++ss) {
                const float* gpx = g_gx + ((size_t)(TS - 2 - s) * 64 + gb0 + ss * 2 + bb) * 1024 + colA;
                gxn[ss] = pk(__ldg(gpx), __ldg(gpx + 256));
            }
        }

#pragma unroll
        for (int ss = 0; ss < 2; ++ss) {
            // per-warp wait: lanes 0..7 each poll one rank's flag
            if (s) {
                if (lane < 8) {
                    const unsigned* fp = &g_flag[layer][grp][ss][lane][0];
                    const unsigned tgt = (unsigned)s;
#pragma unroll 1
                    while (ldacq(fp) < tgt) { }
                }
                __syncwarp();
            }

            // matvec: v[cpi*2 + bbi], k split over i (8 x 32, lane-coalesced)
            ull v[16];
#pragma unroll
            for (int i = 0; i < 8; ++i) {
                float2 h2 = make_float2(0.f, 0.f);
                if (s) h2 = __ldcg((const float2*)&g_hx[cur][grp][ss][i * 32 + lane][0]);
                ull hd0 = dup2(h2.x), hd1 = dup2(h2.y);
                if (i == 0) {
#pragma unroll
                    for (int cpi = 0; cpi < 8; ++cpi) {
                        v[cpi * 2 + 0] = mul2(hd0, wreg[0][cpi]);
                        v[cpi * 2 + 1] = mul2(hd1, wreg[0][cpi]);
                    }
                } else {
#pragma unroll
                    for (int cpi = 0; cpi < 8; ++cpi) {
                        v[cpi * 2 + 0] = fma2(hd0, wreg[i][cpi], v[cpi * 2 + 0]);
                        v[cpi * 2 + 1] = fma2(hd1, wreg[i][cpi], v[cpi * 2 + 1]);
                    }
                }
            }

            // reduce-scatter butterfly (4 rounds) + cross-half merge
#pragma unroll
            for (int t = 0; t < 4; ++t) {
                const int mybit = (lane >> t) & 1;
                const int n = 16 >> t;
#pragma unroll
                for (int i = 0; i < 8; ++i) {
                    if (i < (n >> 1)) {
                        ull lo = v[2 * i], hi = v[2 * i + 1];
                        ull send = mybit ? lo : hi;
                        ull recv = __shfl_xor_sync(0xffffffffu, send, 1 << t);
                        v[i] = add2(mybit ? hi : lo, recv);
                    }
                }
            }
            v[0] = add2(v[0], __shfl_xor_sync(0xffffffffu, v[0], 16));

            // epilogue
            float h1 = 0.f;
            {
                float p0, p1;
                upk(add2(v[0], gxr[ss]), p0, p1);
                float a0 = sigf(p0);
                float a1 = gp ? tanhap(p1) : sigf(p1);
                ull other = __shfl_xor_sync(0xffffffffu, pk(a0, a1), 2);
                if (gp == 0) {
                    float so, tg; upk(other, so, tg);
                    cst[ss] = a0 * cst[ss] + a1 * tg;
                    h1 = so * tanhap(cst[ss]);
                    if (estore && s < TS - 1)
                        g_hx[nxt][grp][ss][jj][bb] = h1;
                }
            }
            gxr[ss] = gxn[ss];

            __syncthreads();          // all h stores of this substep done
            if (s < TS - 1 && tid == 0)
                asm volatile("st.release.gpu.global.u32 [%0], %1;"
                             :: "l"(&g_flag[layer][grp][ss][r][0]),
                                "r"((unsigned)(s + 1)) : "memory");

            // outputs off the critical chain
            if (estore) {
                yout[((size_t)s * 64 + gb0 + ss * 2 + bb) * 256 + jj] = h1;
                if (s == TS - 1) {
                    size_t hi_ = (size_t)(gb0 + ss * 2 + bb) * 256 + jj;
                    hn[hi_] = h1; cn[hi_] = cst[ss];
                }
            }
        }
    }

    // reset flags for the next graph replay (deterministic launches)
    __syncthreads();
    if (tid == 0) {
        asm volatile("red.release.gpu.global.add.u32 [%0], 1;" :: "l"(fin) : "memory");
        if (r == 0) {
#pragma unroll 1
            while (ldacq(fin) < 8u) { }
#pragma unroll
            for (int ss = 0; ss < 2; ++ss)
#pragma unroll
                for (int d = 0; d < 8; ++d)
                    asm volatile("st.global.u32 [%0], %1;"
                                 :: "l"(&g_flag[layer][grp][ss][d][0]), "r"(0u) : "memory");
            asm volatile("st.global.u32 [%0], %1;" :: "l"(fin), "r"(0u) : "memory");
        }
    }
}

extern "C" void kernel_launch(void* const* d_in, const int* in_sizes, int n_in,
                              void* d_out, int out_size)
{
    const float* x    = (const float*)d_in[0];
    const float* wih0 = (const float*)d_in[1];
    const float* whh0 = (const float*)d_in[2];
    const float* b0   = (const float*)d_in[3];
    const float* wih1 = (const float*)d_in[4];
    const float* whh1 = (const float*)d_in[5];
    const float* b1   = (const float*)d_in[6];
    float* out = (float*)d_out;

    dim3 gg(8, 1024);
    gemm_k<<<gg, 256>>>(x, wih0, b0, 128, 0);
    recur_k<<<128, 256>>>(whh0, out, 0);
    gemm_k<<<gg, 256>>>(x, wih1, b1, 256, 1);
    recur_k<<<128, 256>>>(whh1, out, 1);
}

// round 12
// speedup vs baseline: 1.3130x; 1.3130x over previous
#include <cuda_runtime.h>
#include <cstdint>
#include <cstddef>

typedef unsigned long long ull;

#define TS 2048
#define Y1_ELEMS ((size_t)TS * 64 * 256)

// scratch (allocation-free rule)
__device__ float g_gx[(size_t)TS * 64 * 1024];
__device__ float g_y0[(size_t)TS * 64 * 256];
// h exchange through L2: [buf][group][k][batch]
__device__ float g_hx[2][16][256][4];
// per-layer, per-group, PER-RANK monotonic flags (each on own 128B line)
__device__ __align__(128) unsigned g_flag[2][16][8][32];
__device__ __align__(128) unsigned g_fin[2][16][32];

__device__ __forceinline__ ull fma2(ull a, ull b, ull c) {
    ull d; asm("fma.rn.f32x2 %0,%1,%2,%3;" : "=l"(d) : "l"(a), "l"(b), "l"(c)); return d;
}
__device__ __forceinline__ ull mul2(ull a, ull b) {
    ull d; asm("mul.rn.f32x2 %0,%1,%2;" : "=l"(d) : "l"(a), "l"(b)); return d;
}
__device__ __forceinline__ ull add2(ull a, ull b) {
    ull d; asm("add.rn.f32x2 %0,%1,%2;" : "=l"(d) : "l"(a), "l"(b)); return d;
}
__device__ __forceinline__ ull pk(float lo, float hi) {
    ull r; asm("mov.b64 %0,{%1,%2};" : "=l"(r) : "f"(lo), "f"(hi)); return r;
}
__device__ __forceinline__ void upk(ull a, float& x, float& y) {
    asm("mov.b64 {%0,%1},%2;" : "=f"(x), "=f"(y) : "l"(a));
}
__device__ __forceinline__ ull dup2(float x) {
    ull r; asm("mov.b64 %0,{%1,%1};" : "=l"(r) : "f"(x)); return r;
}
__device__ __forceinline__ float ex2f(float x) {
    float r; asm("ex2.approx.f32 %0,%1;" : "=f"(r) : "f"(x)); return r;
}
__device__ __forceinline__ float rcpf(float x) {
    float r; asm("rcp.approx.f32 %0,%1;" : "=f"(r) : "f"(x)); return r;
}
__device__ __forceinline__ float sigf(float x) {
    return rcpf(1.f + ex2f(-1.44269504f * x));
}
__device__ __forceinline__ float tanhap(float x) {
    float r; asm("tanh.approx.f32 %0,%1;" : "=f"(r) : "f"(x)); return r;
}
__device__ __forceinline__ unsigned ldacq(const unsigned* p) {
    unsigned v;
    asm volatile("ld.acquire.gpu.global.u32 %0,[%1];" : "=r"(v) : "l"(p) : "memory");
    return v;
}

// ---------------------------------------------------------------------------
// GEMM: g_gx[m][n] = A_row(m) . W[:,n] + bias[n],  M = TS*64, N = 1024
// mode 0: A_row(m) = x + ((m&63)*TS + (m>>6))*128, K=128
// mode 1: A_row(m) = g_y0 + m*256,                 K=256
// ---------------------------------------------------------------------------
__global__ void __launch_bounds__(256, 1)
gemm_k(const float* __restrict__ A, const float* __restrict__ W,
       const float* __restrict__ bias, int K, int mode)
{
    __shared__ float As[16][132];
    __shared__ float Bs[16][128];

    const int tid = threadIdx.x;
    const int n0 = blockIdx.x * 128;
    const int m0 = blockIdx.y * 128;

    const int ar = tid >> 1;
    const int ac = (tid & 1) * 8;
    const int m = m0 + ar;
    const float* arow = mode ? (g_y0 + (size_t)m * 256)
                             : (A + ((size_t)(m & 63) * TS + (m >> 6)) * 128);
    const float* wp = W + (size_t)(tid >> 4) * 1024 + n0 + (tid & 15) * 8;

    const int tm = tid >> 4, tn = tid & 15;

    ull acc[8][4];
#pragma unroll
    for (int i = 0; i < 8; ++i)
#pragma unroll
        for (int j = 0; j < 4; ++j) acc[i][j] = 0ull;

#pragma unroll 1
    for (int k0 = 0; k0 < K; k0 += 16) {
        float4 a0 = *(const float4*)(arow + k0 + ac);
        float4 a1 = *(const float4*)(arow + k0 + ac + 4);
        float4 w0 = *(const float4*)(wp + (size_t)k0 * 1024);
        float4 w1 = *(const float4*)(wp + (size_t)k0 * 1024 + 4);
        __syncthreads();
        As[ac + 0][ar] = a0.x; As[ac + 1][ar] = a0.y;
        As[ac + 2][ar] = a0.z; As[ac + 3][ar] = a0.w;
        As[ac + 4][ar] = a1.x; As[ac + 5][ar] = a1.y;
        As[ac + 6][ar] = a1.z; As[ac + 7][ar] = a1.w;
        *(float4*)&Bs[tid >> 4][(tid & 15) * 8] = w0;
        *(float4*)&Bs[tid >> 4][(tid & 15) * 8 + 4] = w1;
        __syncthreads();
#pragma unroll
        for (int kk = 0; kk < 16; ++kk) {
            float4 av0 = *(const float4*)&As[kk][tm * 8];
            float4 av1 = *(const float4*)&As[kk][tm * 8 + 4];
            float av[8] = {av0.x, av0.y, av0.z, av0.w, av1.x, av1.y, av1.z, av1.w};
            const ull* bp = (const ull*)&Bs[kk][0];
            ull bv[4];
#pragma unroll
            for (int c = 0; c < 4; ++c) bv[c] = bp[tn * 4 + c];
#pragma unroll
            for (int r = 0; r < 8; ++r) {
                ull a2 = dup2(av[r]);
#pragma unroll
                for (int c = 0; c < 4; ++c) acc[r][c] = fma2(a2, bv[c], acc[r][c]);
            }
        }
    }

    float bb[8];
#pragma unroll
    for (int c = 0; c < 8; ++c) bb[c] = bias[n0 + tn * 8 + c];

#pragma unroll
    for (int r = 0; r < 8; ++r) {
        float v[8];
#pragma unroll
        for (int c = 0; c < 4; ++c) upk(acc[r][c], v[2 * c], v[2 * c + 1]);
#pragma unroll
        for (int c = 0; c < 8; ++c) v[c] += bb[c];
        float* op = g_gx + (size_t)(m0 + tm * 8 + r) * 1024 + n0 + tn * 8;
        *(float4*)op = make_float4(v[0], v[1], v[2], v[3]);
        *(float4*)(op + 4) = make_float4(v[4], v[5], v[6], v[7]);
    }
}

// ---------------------------------------------------------------------------
// Recurrence (R10 skeleton + memory hygiene):
// 128 CTAs; group g = blockIdx>>3 (8 CTAs), rank r = blockIdx&7.
// Group handles batches [g*4, g*4+4). Rank owns units [r*32, r*32+32).
// Warp w owns 4 units x 4 gates x 4 batches, all k. Lane l: k = i*32+l.
// Changes vs R10:
//  - gx loaded COALESCED (1 LDG.64/thread, one step ahead) into double-
//    buffered smem gxs; epilogue reads LDS.64. Kills ~400 scattered L1tex
//    wavefronts + DRAM read amplification per step.
//  - yout staged in smem, written as four 128B coalesced rows post-publish.
//  - consumer wait is PER-WARP (lanes 0..7 poll + syncwarp); producer-side
//    __syncthreads before the release remains (also fences the staging).
// ---------------------------------------------------------------------------
__global__ void __launch_bounds__(256, 1)
recur_k(const float* __restrict__ whh, float* __restrict__ out, int layer)
{
    __shared__ float gxs[2][4][32][4];   // [buf][batch][unit_local][gate]
    __shared__ float ysm[4][33];         // [batch][unit_local] (padded)

    const int tid  = threadIdx.x;
    const int w    = tid >> 5;
    const int lane = tid & 31;
    const int grp  = blockIdx.x >> 3;
    const int r    = blockIdx.x & 7;
    const int gb0  = grp * 4;

    // epilogue identity
    const int cp = lane >> 2;          // col-pair 0..7
    const int b  = lane & 3;           // batch 0..3
    const int gp = cp & 1;             // 0 -> (f,i), 1 -> (o,g)
    const int u  = cp >> 1;            // unit-local in warp 0..3
    const int jj = r * 32 + w * 4 + u;

    // gx loader identity: 2 consecutive floats per thread
    const int b2    = tid >> 6;        // batch 0..3
    const int gate2 = (tid >> 4) & 3;  // gate 0..3
    const int u2    = tid & 15;        // unit pair 0..15
    const size_t gx_off = (size_t)(gb0 + b2) * 1024 + gate2 * 256 + r * 32 + 2 * u2;

    // weights: wreg[i][cp] for k = i*32 + lane, cols (cA, cA+256)
    ull wreg[8][8];
#pragma unroll
    for (int i = 0; i < 8; ++i) {
        const int k = i * 32 + lane;
#pragma unroll
        for (int cpi = 0; cpi < 8; ++cpi) {
            const int cA = (2 * (cpi & 1)) * 256 + r * 32 + w * 4 + (cpi >> 1);
            const float* wp = whh + (size_t)k * 1024 + cA;
            wreg[i][cpi] = pk(wp[0], wp[256]);
        }
    }

    unsigned* myflag = &g_flag[layer][grp][r][0];
    unsigned* fin    = &g_fin[layer][grp][0];

    float cst = 0.f;
    float* yout = layer ? out : g_y0;
    float* hn = out + Y1_ELEMS + (size_t)layer * 16384;
    float* cn = out + Y1_ELEMS + 32768 + (size_t)layer * 16384;

    // preload step-0 gx into gxs[0]
    {
        float2 g0 = __ldg((const float2*)(g_gx + (size_t)(TS - 1) * 64 * 1024 + gx_off));
        gxs[0][b2][2 * u2][gate2]     = g0.x;
        gxs[0][b2][2 * u2 + 1][gate2] = g0.y;
    }
    __syncthreads();

#pragma unroll 1
    for (int s = 0; s < TS; ++s) {
        const int cur = s & 1;
        const int nxt = cur ^ 1;

        // coalesced prefetch of next step's gx (consumed next iteration)
        float2 gld = make_float2(0.f, 0.f);
        if (s + 1 < TS)
            gld = __ldg((const float2*)(g_gx + (size_t)(TS - 2 - s) * 64 * 1024 + gx_off));

        // per-warp wait: lanes 0..7 each poll one rank's flag
        if (s) {
            if (lane < 8) {
                const unsigned* fp = &g_flag[layer][grp][lane][0];
                const unsigned tgt = (unsigned)s;
#pragma unroll 1
                while (ldacq(fp) < tgt) { }
            }
            __syncwarp();
        }

        // matvec: v[cp*4 + bb]; h read straight from L2 (step 0: h = 0)
        ull v[32];
#pragma unroll
        for (int i = 0; i < 8; ++i) {
            float4 h4 = make_float4(0.f, 0.f, 0.f, 0.f);
            if (s) h4 = __ldcg((const float4*)&g_hx[cur][grp][i * 32 + lane][0]);
            ull hd0 = dup2(h4.x), hd1 = dup2(h4.y), hd2 = dup2(h4.z), hd3 = dup2(h4.w);
            if (i == 0) {
#pragma unroll
                for (int cpi = 0; cpi < 8; ++cpi) {
                    v[cpi * 4 + 0] = mul2(hd0, wreg[0][cpi]);
                    v[cpi * 4 + 1] = mul2(hd1, wreg[0][cpi]);
                    v[cpi * 4 + 2] = mul2(hd2, wreg[0][cpi]);
                    v[cpi * 4 + 3] = mul2(hd3, wreg[0][cpi]);
                }
            } else {
#pragma unroll
                for (int cpi = 0; cpi < 8; ++cpi) {
                    v[cpi * 4 + 0] = fma2(hd0, wreg[i][cpi], v[cpi * 4 + 0]);
                    v[cpi * 4 + 1] = fma2(hd1, wreg[i][cpi], v[cpi * 4 + 1]);
                    v[cpi * 4 + 2] = fma2(hd2, wreg[i][cpi], v[cpi * 4 + 2]);
                    v[cpi * 4 + 3] = fma2(hd3, wreg[i][cpi], v[cpi * 4 + 3]);
                }
            }
        }

        // reduce-scatter butterfly: lane l ends holding (cp=l>>2, b=l&3)
#pragma unroll
        for (int t = 0; t < 5; ++t) {
            const int mybit = (lane >> t) & 1;
            const int n = 32 >> t;
#pragma unroll
            for (int i = 0; i < 16; ++i) {
                if (i < (n >> 1)) {
                    ull lo = v[2 * i], hi = v[2 * i + 1];
                    ull send = mybit ? lo : hi;
                    ull recv = __shfl_xor_sync(0xffffffffu, send, 1 << t);
                    v[i] = add2(mybit ? hi : lo, recv);
                }
            }
        }

        // stage next step's gx into the other smem buffer
        if (s + 1 < TS) {
            gxs[nxt][b2][2 * u2][gate2]     = gld.x;
            gxs[nxt][b2][2 * u2 + 1][gate2] = gld.y;
        }

        // epilogue: compute h; stage h for coalesced output; STG h for peers
        float h1 = 0.f;
        {
            float2 gx2 = *(const float2*)&gxs[cur][b][w * 4 + u][2 * gp];
            float p0, p1; upk(v[0], p0, p1);
            p0 += gx2.x; p1 += gx2.y;
            float a0 = sigf(p0);
            float a1 = gp ? tanhap(p1) : sigf(p1);
            ull other = __shfl_xor_sync(0xffffffffu, pk(a0, a1), 4);
            if (gp == 0) {
                float so, tg; upk(other, so, tg);
                cst = a0 * cst + a1 * tg;
                h1 = so * tanhap(cst);
                if (s < TS - 1)
                    g_hx[nxt][grp][jj][b] = h1;
                ysm[b][w * 4 + u] = h1;
            }
        }

        __syncthreads();              // h + staging stores happen-before release
        if (s < TS - 1 && tid == 0)
            asm volatile("st.release.gpu.global.u32 [%0], %1;"
                         :: "l"(myflag), "r"((unsigned)(s + 1)) : "memory");

        // coalesced outputs — off the critical chain
        if (w < 4)
            yout[((size_t)s * 64 + gb0 + w) * 256 + r * 32 + lane] = ysm[w][lane];
        if (s == TS - 1 && gp == 0) {
            size_t hi_ = (size_t)(gb0 + b) * 256 + jj;
            hn[hi_] = h1; cn[hi_] = cst;
        }
    }

    // reset flags for the next graph replay (deterministic launches)
    __syncthreads();
    if (tid == 0) {
        asm volatile("red.release.gpu.global.add.u32 [%0], 1;" :: "l"(fin) : "memory");
        if (r == 0) {
#pragma unroll 1
            while (ldacq(fin) < 8u) { }
#pragma unroll
            for (int d = 0; d < 8; ++d)
                asm volatile("st.global.u32 [%0], %1;"
                             :: "l"(&g_flag[layer][grp][d][0]), "r"(0u) : "memory");
            asm volatile("st.global.u32 [%0], %1;" :: "l"(fin), "r"(0u) : "memory");
        }
    }
}

extern "C" void kernel_launch(void* const* d_in, const int* in_sizes, int n_in,
                              void* d_out, int out_size)
{
    const float* x    = (const float*)d_in[0];
    const float* wih0 = (const float*)d_in[1];
    const float* whh0 = (const float*)d_in[2];
    const float* b0   = (const float*)d_in[3];
    const float* wih1 = (const float*)d_in[4];
    const float* whh1 = (const float*)d_in[5];
    const float* b1   = (const float*)d_in[6];
    float* out = (float*)d_out;

    dim3 gg(8, 1024);
    gemm_k<<<gg, 256>>>(x, wih0, b0, 128, 0);
    recur_k<<<128, 256>>>(whh0, out, 0);
    gemm_k<<<gg, 256>>>(x, wih1, b1, 256, 1);
    recur_k<<<128, 256>>>(whh1, out, 1);
}